// round 11
// baseline (speedup 1.0000x reference)
#include <cuda_runtime.h>
#include <cstdint>

typedef uint32_t u32; typedef unsigned long long u64;
#define TPB 256

// ---- smem byte offsets (identical to round-10) ----
#define S_A0   0
#define S_A1   16384
#define S_B0   32768
#define S_B1   65536
#define S_SIG  0          // sigma frags 128KB (overlaps dead mainloop bufs)
#define S_VH   131072     // 3 x 16KB tf32 V_h frag tiles
#define S_BG   180224     // gate B stream 32KB
#define S_WMU  212992     // 4KB
#define S_WH   217088     // 4KB
#define S_BIAS 221184     // 1KB
#define S_WGB  222208     // 128B
#define SMEM_TOTAL 222336
#define S_VT0  0
#define S_VT1  16384
#define S_VT2  65536

// Pre-rounded, quad-packed weights (same format as round-10).
__device__ u32 g_Bm[9*8192];
__device__ u32 g_Bg[8*1024];
__device__ u32 g_Bh[1024];
__device__ u32 g_Bmu[1024];

__device__ __forceinline__ u32 rna(float x){u32 u;asm("cvt.rna.tf32.f32 %0,%1;":"=r"(u):"f"(x));return u;}

__global__ void prep(const float* __restrict__ Wm, const float* __restrict__ Wg,
                     const float* __restrict__ Wh, const float* __restrict__ Wmu){
    int i = blockIdx.x*blockDim.x + threadIdx.x;
    if (i < 73728){
        int c=i>>13, r=i&8191, q=r>>2, j=r&3, lane=q&31, t2=q>>5, kh=t2&1, nt=t2>>1;
        g_Bm[i] = rna(Wm[(nt*8+(lane>>2))*288 + c*32 + kh*16 + (j>>1)*8 + (lane&3) + (j&1)*4]);
    } else if (i < 81920){
        int p=i-73728, c2=p>>10, r=p&1023, q=r>>2, j=r&3, lane=q&31, t2=q>>5, kh=t2&1, nt=t2>>1;
        g_Bg[p] = rna(Wg[(nt*8+(lane>>2))*256 + c2*32 + kh*16 + (j>>1)*8 + (lane&3) + (j&1)*4]);
    } else if (i < 82944){
        int p=i-81920, q=p>>2, j=p&3, lane=q&31, t2=q>>5, kh=t2&1, nt=t2>>1;
        g_Bh[p] = rna(Wh[(nt*8+(lane>>2))*32 + kh*16 + (j>>1)*8 + (lane&3) + (j&1)*4]);
    } else if (i < 83968){
        int p=i-82944, q=p>>2, j=p&3, lane=q&31, t2=q>>5, kh=t2&1, nt=t2>>1;
        g_Bmu[p] = rna(Wmu[(nt*8+(lane>>2))*32 + kh*16 + (j>>1)*8 + (lane&3) + (j&1)*4]);
    }
}

__device__ __forceinline__ void mma8(float* d, const u32* a, u32 b0, u32 b1){
    asm volatile("mma.sync.aligned.m16n8k8.row.col.f32.tf32.tf32.f32 "
        "{%0,%1,%2,%3},{%4,%5,%6,%7},{%8,%9},{%0,%1,%2,%3};"
        : "+f"(d[0]),"+f"(d[1]),"+f"(d[2]),"+f"(d[3])
        : "r"(a[0]),"r"(a[1]),"r"(a[2]),"r"(a[3]),"r"(b0),"r"(b1));
}
__device__ __forceinline__ u32 smem_u32(const void* p){
    u32 a;asm("{ .reg .u64 t; cvta.to.shared.u64 t,%1; cvt.u32.u64 %0,t; }":"=r"(a):"l"(p));return a;}
__device__ __forceinline__ void cpasync16(u32 d, const void* s){
    asm volatile("cp.async.cg.shared.global [%0], [%1], 16;"::"r"(d),"l"(s):"memory");}
#define CP_COMMIT asm volatile("cp.async.commit_group;":::"memory")
#define CP_WAIT(n) asm volatile("cp.async.wait_group %0;"::"n"(n):"memory")
#define LDS128(r, ad) asm volatile("ld.shared.v4.u32 {%0,%1,%2,%3},[%4];" \
  : "=r"((r)[0]),"=r"((r)[1]),"=r"((r)[2]),"=r"((r)[3]) : "r"(ad))
#define STS64(ad, x, y) asm volatile("st.shared.v2.u32 [%0],{%1,%2};" :: "r"(ad),"r"(x),"r"(y) : "memory")
#define STS32(ad, x) asm volatile("st.shared.u32 [%0],%1;" :: "r"(ad),"r"(x) : "memory")
__device__ __forceinline__ float sigm(float x){return 1.f/(1.f+__expf(-x));}

__global__ void __launch_bounds__(TPB,1) gvp_kernel(
    const float* __restrict__ s_g, const float* __restrict__ V_g,
    const float* __restrict__ Wmb, const float* __restrict__ Wgb,
    float* __restrict__ out, int N)
{
    extern __shared__ char smc[];
    const u32 smb = smem_u32(smc);
    const int t = threadIdx.x, lane = t&31, w = t>>5;     // 8 warps
    const int wm = w>>2, wn = w&3;     // main GEMM: warp tile 64 rows x 64 cols
    const int r7 = lane>>2, c4 = lane&3;
    const int node0 = blockIdx.x*128;

    // A-staging producer: f = t + 256*h (h=0..3) -> (row = f>>3, k4 = t&7)
    const int ak4 = t&7;

    // ---- prologue ----
    if (t < 64) ((float4*)(smc+S_BIAS))[t] = ((const float4*)Wmb)[t];
    if (t >= 64 && t < 72) ((float4*)(smc+S_WGB))[t-64] = ((const float4*)Wgb)[t-64];
    ((float4*)(smc+S_WMU))[t] = ((const float4*)g_Bmu)[t];
    ((float4*)(smc+S_WH))[t]  = ((const float4*)g_Bh)[t];
    #pragma unroll
    for (int q=0;q<8;q++)   // B chunk0 -> B0 (lands during V_h phase)
        cpasync16(smb + S_B0 + (t+256*q)*16, g_Bm + (t+256*q)*4);
    CP_COMMIT;

    // V scatter into 3 component A-frag tiles
    const u32 vtOff[3] = {S_VT0, S_VT1, S_VT2};
    #pragma unroll
    for (int q=0;q<12;q++){
        int g = t + 256*q, node = g/24, jj = g - node*24;
        float4 v4 = ((const float4*)V_g)[(size_t)(node0+node)*24 + jj];
        float vv[4] = {v4.x, v4.y, v4.z, v4.w};
        int mt = node>>4, rt = node&15;
        #pragma unroll
        for (int e=0;e<4;e++){
            int f = jj*4+e, vi = f/3, comp = f - vi*3;
            int lp = (rt&7)*4 + (vi&3);
            int jq = ((rt>>3)&1) + ((vi&4)?2:0);
            *(u32*)(smc + vtOff[comp] + (((mt*4+(vi>>3))*32 + lp)*4 + jq)*4) = rna(vv[e]);
        }
    }
    // A chunk0 prefetch (coalesced LDG.128, 4 per thread)
    float4 apf[4];
    #pragma unroll
    for (int h=0;h<4;h++)
        apf[h] = *(const float4*)(s_g + (size_t)(node0+((t+256*h)>>3))*256 + ak4*4);
    __syncthreads();

    // ---- V_h mma: warp w owns rows w*16..+15, all 4 n-tiles ----
    float vh[3][4][4];
    #pragma unroll
    for(int c=0;c<3;c++)for(int n2=0;n2<4;n2++)for(int e=0;e<4;e++) vh[c][n2][e]=0.f;
    #pragma unroll
    for (int c=0;c<3;c++)
    #pragma unroll
    for (int ks=0;ks<4;ks++){
        u32 a[4]; LDS128(a, smb + vtOff[c] + ((w*4+ks)*32+lane)*16);
        #pragma unroll
        for (int n2=0;n2<4;n2++){
            u32 bq[4]; LDS128(bq, smb + S_WH + ((n2*2+(ks>>1))*32+lane)*16);
            mma8(vh[c][n2], a, bq[(ks&1)*2], bq[(ks&1)*2+1]);
        }
    }
    // norm -> sh regs (chunk-8 A) + V_h tf32 frag tiles (mt = w)
    u32 shq[16];
    #pragma unroll
    for (int n2=0;n2<4;n2++)
    #pragma unroll
    for (int e=0;e<4;e++){
        float x=vh[0][n2][e], y=vh[1][n2][e], z=vh[2][n2][e];
        shq[n2*4+e] = rna(fmaxf(sqrtf(x*x+y*y+z*z), 1e-4f));
        int h = n2*8 + 2*c4 + (e&1);
        int rt = r7 + ((e>>1)<<3);
        int lp = (rt&7)*4 + (h&3);
        int jq = ((rt>>3)&1) + ((h&4)?2:0);
        u32 idx = (((w*4+(h>>3))*32 + lp)*4 + jq)*4;
        *(u32*)(smc + S_VH         + idx) = rna(x);
        *(u32*)(smc + S_VH + 16384 + idx) = rna(y);
        *(u32*)(smc + S_VH + 32768 + idx) = rna(z);
    }
    __syncthreads();   // V-tile reads done; S_A0/S_A1/S_B1 now free

    // ---- pre-stage chunk 0 A, prefetch chunk 1 A ----
    #pragma unroll
    for (int h=0;h<4;h++){
        int row = (t+256*h)>>3;
        int mt = row>>4, rt = row&15;
        int jq = ((rt>>3)&1) + ((ak4&1)?2:0);
        float vv[4] = {apf[h].x, apf[h].y, apf[h].z, apf[h].w};
        u32 base = smb + S_A0 + (((mt*4+(ak4>>1))*32 + (rt&7)*4)*4 + jq)*4;
        #pragma unroll
        for (int s=0;s<4;s++){
            int e = (s + ak4 + rt) & 3;
            STS32(base + e*16, rna(vv[e]));
        }
    }
    #pragma unroll
    for (int h=0;h<4;h++)
        apf[h] = *(const float4*)(s_g + (size_t)(node0+((t+256*h)>>3))*256 + 32 + ak4*4);
    CP_WAIT(0);        // B0 landed
    __syncthreads();

    // ---- main GEMM: 9 chunks, warp tile 64x64, overlapped staging ----
    float acc[4][8][4];
    #pragma unroll
    for(int i=0;i<4;i++)for(int j=0;j<8;j++)for(int e=0;e<4;e++) acc[i][j][e]=0.f;

    for (int c=0;c<9;c++){
        int buf = c&1;
        u32 aOff = buf? S_A1:S_A0, bRd  = buf? S_B1:S_B0;
        u32 aNxt = buf? S_A0:S_A1, bNxt = buf? S_B0:S_B1;

        if (c < 7){
            #pragma unroll
            for (int h=0;h<4;h++){
                int row = (t+256*h)>>3;
                int mt = row>>4, rt = row&15;
                int jq = ((rt>>3)&1) + ((ak4&1)?2:0);
                float vv[4] = {apf[h].x, apf[h].y, apf[h].z, apf[h].w};
                u32 base = smb + aNxt + (((mt*4+(ak4>>1))*32 + (rt&7)*4)*4 + jq)*4;
                #pragma unroll
                for (int s=0;s<4;s++){
                    int e = (s + ak4 + rt) & 3;
                    STS32(base + e*16, rna(vv[e]));
                }
            }
        } else if (c == 7){   // chunk 8 = s_h from regs (mt = w rows)
            #pragma unroll
            for (int n2=0;n2<4;n2++)
            #pragma unroll
            for (int e=0;e<4;e++){
                int h = n2*8 + 2*c4 + (e&1);
                int rt = r7 + ((e>>1)<<3);
                int lp = (rt&7)*4 + (h&3);
                int jq = ((rt>>3)&1) + ((h&4)?2:0);
                *(u32*)(smc + aNxt + (((w*4+(h>>3))*32 + lp)*4 + jq)*4) = shq[n2*4+e];
            }
        }
        if (c < 6){
            #pragma unroll
            for (int h=0;h<4;h++)
                apf[h] = *(const float4*)(s_g + (size_t)(node0+((t+256*h)>>3))*256 + (c+2)*32 + ak4*4);
        }
        if (c < 8){
            const u32* src = g_Bm + (c+1)*8192;
            #pragma unroll
            for (int q=0;q<8;q++)
                cpasync16(smb + bNxt + (t+256*q)*16, src + (t+256*q)*4);
            CP_COMMIT;
        } else {
            #pragma unroll
            for (int q=0;q<8;q++)
                cpasync16(smb + S_BG + (t+256*q)*16, g_Bg + (t+256*q)*4);
            CP_COMMIT;
        }

        // -- compute chunk c: 64x64 tile, 64 mma --
        #pragma unroll
        for (int kh=0;kh<2;kh++){
            u32 b[8][4];
            #pragma unroll
            for (int j2=0;j2<8;j2++)
                LDS128(b[j2], smb + bRd + (((wn*8+j2)*2+kh)*32+lane)*16);
            #pragma unroll
            for (int ks2=0;ks2<2;ks2++){
                int ks = kh*2+ks2;
                u32 a[4][4];
                #pragma unroll
                for (int i=0;i<4;i++)
                    LDS128(a[i], smb + aOff + (((wm*4+i)*4+ks)*32+lane)*16);
                #pragma unroll
                for (int i=0;i<4;i++)
                    #pragma unroll
                    for (int j2=0;j2<8;j2++)
                        mma8(acc[i][j2], a[i], b[j2][ks2*2], b[j2][ks2*2+1]);
            }
        }
        CP_WAIT(0);
        __syncthreads();
    }

    // ---- epilogue: relu store + sigma frags ----
    float2 bi[8];
    #pragma unroll
    for (int j2=0;j2<8;j2++)
        bi[j2] = *(const float2*)(smc + S_BIAS + (wn*64 + j2*8 + c4*2)*4);

    #pragma unroll
    for (int i=0;i<4;i++)
    #pragma unroll
    for (int j2=0;j2<8;j2++){
        int C = wn*64 + j2*8 + c4*2;
        size_t R = (size_t)node0 + wm*64 + i*16 + r7;
        float m0=acc[i][j2][0]+bi[j2].x, m1=acc[i][j2][1]+bi[j2].y;
        float m2=acc[i][j2][2]+bi[j2].x, m3=acc[i][j2][3]+bi[j2].y;
        float2 o0 = {fmaxf(m0,0.f), fmaxf(m1,0.f)};
        float2 o1 = {fmaxf(m2,0.f), fmaxf(m3,0.f)};
        *(float2*)(out + R*256 + C) = o0;
        *(float2*)(out + (R+8)*256 + C) = o1;
        u32 s0=rna(sigm(m0)), s1=rna(sigm(m1)), s2=rna(sigm(m2)), s3=rna(sigm(m3));
        int kseq = C>>3, c8 = C&7, mt = wm*4+i;
        u32 a0 = smb + S_SIG + ((u32)((mt*32+kseq)*32 + r7*4 + (c8&3)))*16 + ((c8&4)?8:0);
        STS64(a0, s0, s2);
        int c8b = c8+1;
        u32 a1 = smb + S_SIG + ((u32)((mt*32+kseq)*32 + r7*4 + (c8b&3)))*16 + ((c8b&4)?8:0);
        STS64(a1, s1, s3);
    }
    __syncthreads();

    // gate GEMM: warp w owns rows w*16..+15, all 4 n-tiles (no A duplication)
    float gacc[4][4];
    #pragma unroll
    for(int n2=0;n2<4;n2++)for(int e=0;e<4;e++) gacc[n2][e]=0.f;
    for (int kc=0;kc<8;kc++){
        #pragma unroll
        for (int kh=0;kh<2;kh++){
            u32 b[4][4];
            #pragma unroll
            for (int n2=0;n2<4;n2++)
                LDS128(b[n2], smb + S_BG + kc*4096 + ((n2*2+kh)*32+lane)*16);
            #pragma unroll
            for (int ks2=0;ks2<2;ks2++){
                int kseq = kc*4 + kh*2 + ks2;
                u32 a[4]; LDS128(a, smb + S_SIG + ((w*32+kseq)*32+lane)*16);
                #pragma unroll
                for (int n2=0;n2<4;n2++)
                    mma8(gacc[n2], a, b[n2][ks2*2], b[n2][ks2*2+1]);
            }
        }
    }
    // V_mu mma from VH frag tiles (warp w rows)
    float vm[3][4][4];
    #pragma unroll
    for(int c=0;c<3;c++)for(int n2=0;n2<4;n2++)for(int e=0;e<4;e++) vm[c][n2][e]=0.f;
    #pragma unroll
    for (int c3=0;c3<3;c3++)
    #pragma unroll
    for (int ks=0;ks<4;ks++){
        u32 a[4]; LDS128(a, smb + S_VH + c3*16384 + ((w*4+ks)*32+lane)*16);
        #pragma unroll
        for (int n2=0;n2<4;n2++){
            u32 bq[4]; LDS128(bq, smb + S_WMU + ((n2*2+(ks>>1))*32+lane)*16);
            mma8(vm[c3][n2], a, bq[(ks&1)*2], bq[(ks&1)*2+1]);
        }
    }
    // final: V_dash = sigmoid(gate logits + b) * V_mu
    #pragma unroll
    for (int n2=0;n2<4;n2++){
        int m0c = n2*8 + c4*2;
        float wg0 = *(const float*)(smc + S_WGB + m0c*4);
        float wg1 = *(const float*)(smc + S_WGB + (m0c+1)*4);
        #pragma unroll
        for (int h2=0;h2<2;h2++){
            int e0 = h2*2;
            float g0 = sigm(gacc[n2][e0]   + wg0);
            float g1 = sigm(gacc[n2][e0+1] + wg1);
            size_t node = (size_t)node0 + w*16 + r7 + h2*8;
            float* p = out + (size_t)N*256 + node*96 + m0c*3;
            float2 q0 = {g0*vm[0][n2][e0],   g0*vm[1][n2][e0]};
            float2 q1 = {g0*vm[2][n2][e0],   g1*vm[0][n2][e0+1]};
            float2 q2 = {g1*vm[1][n2][e0+1], g1*vm[2][n2][e0+1]};
            *(float2*)p = q0; *(float2*)(p+2) = q1; *(float2*)(p+4) = q2;
        }
    }
}

extern "C" void kernel_launch(void* const* d_in, const int* in_sizes, int n_in,
                              void* d_out, int out_size) {
    const float* s   = (const float*)d_in[0];
    const float* V   = (const float*)d_in[1];
    const float* Wh  = (const float*)d_in[2];
    const float* Wmu = (const float*)d_in[3];
    const float* Wm  = (const float*)d_in[4];
    const float* Wmb = (const float*)d_in[5];
    const float* Wg  = (const float*)d_in[6];
    const float* Wgb = (const float*)d_in[7];
    float* out = (float*)d_out;
    const int N = in_sizes[0] / 256;

    cudaFuncSetAttribute(gvp_kernel, cudaFuncAttributeMaxDynamicSharedMemorySize, SMEM_TOTAL);
    prep<<<(83968+255)/256, 256>>>(Wm, Wg, Wh, Wmu);
    gvp_kernel<<<N/128, TPB, SMEM_TOTAL>>>(s, V, Wmb, Wgb, out, N);
}

// round 12
// speedup vs baseline: 1.1293x; 1.1293x over previous
#include <cuda_runtime.h>
#include <cstdint>

typedef uint32_t u32; typedef unsigned long long u64;
#define TPB 256

// ---- smem byte offsets (64-node CTA, total ~105KB -> 2 CTAs/SM) ----
#define S_A0   0          // 8KB  (64x32 tf32 frag tile)
#define S_A1   8192       // 8KB
#define S_B0   16384      // 32KB
#define S_B1   49152      // 32KB   mainloop region [0,81920)
#define S_SIG  0          // sigma frags 64KB (overlaps dead mainloop bufs)
#define S_VH   81920      // 3 x 8KB tf32 V_h frag tiles
#define S_BIAS 106496     // 1KB
#define S_WGB  107520     // 128B
#define SMEM_TOTAL 107648
// V component tiles (prologue only): A0, A1, first 8KB of B1 (B0 holds chunk0 cp.async)
#define S_VT0  S_A0
#define S_VT1  S_A1
#define S_VT2  S_B1

// Pre-rounded, quad-packed weights (format unchanged from rounds 8-11).
__device__ u32 g_Bm[9*8192];
__device__ u32 g_Bg[8*1024];
__device__ u32 g_Bh[1024];
__device__ u32 g_Bmu[1024];

__device__ __forceinline__ u32 rna(float x){u32 u;asm("cvt.rna.tf32.f32 %0,%1;":"=r"(u):"f"(x));return u;}

__global__ void prep(const float* __restrict__ Wm, const float* __restrict__ Wg,
                     const float* __restrict__ Wh, const float* __restrict__ Wmu){
    int i = blockIdx.x*blockDim.x + threadIdx.x;
    if (i < 73728){
        int c=i>>13, r=i&8191, q=r>>2, j=r&3, lane=q&31, t2=q>>5, kh=t2&1, nt=t2>>1;
        g_Bm[i] = rna(Wm[(nt*8+(lane>>2))*288 + c*32 + kh*16 + (j>>1)*8 + (lane&3) + (j&1)*4]);
    } else if (i < 81920){
        int p=i-73728, c2=p>>10, r=p&1023, q=r>>2, j=r&3, lane=q&31, t2=q>>5, kh=t2&1, nt=t2>>1;
        g_Bg[p] = rna(Wg[(nt*8+(lane>>2))*256 + c2*32 + kh*16 + (j>>1)*8 + (lane&3) + (j&1)*4]);
    } else if (i < 82944){
        int p=i-81920, q=p>>2, j=p&3, lane=q&31, t2=q>>5, kh=t2&1, nt=t2>>1;
        g_Bh[p] = rna(Wh[(nt*8+(lane>>2))*32 + kh*16 + (j>>1)*8 + (lane&3) + (j&1)*4]);
    } else if (i < 83968){
        int p=i-82944, q=p>>2, j=p&3, lane=q&31, t2=q>>5, kh=t2&1, nt=t2>>1;
        g_Bmu[p] = rna(Wmu[(nt*8+(lane>>2))*32 + kh*16 + (j>>1)*8 + (lane&3) + (j&1)*4]);
    }
}

__device__ __forceinline__ void mma8(float* d, const u32* a, u32 b0, u32 b1){
    asm volatile("mma.sync.aligned.m16n8k8.row.col.f32.tf32.tf32.f32 "
        "{%0,%1,%2,%3},{%4,%5,%6,%7},{%8,%9},{%0,%1,%2,%3};"
        : "+f"(d[0]),"+f"(d[1]),"+f"(d[2]),"+f"(d[3])
        : "r"(a[0]),"r"(a[1]),"r"(a[2]),"r"(a[3]),"r"(b0),"r"(b1));
}
__device__ __forceinline__ u32 smem_u32(const void* p){
    u32 a;asm("{ .reg .u64 t; cvta.to.shared.u64 t,%1; cvt.u32.u64 %0,t; }":"=r"(a):"l"(p));return a;}
__device__ __forceinline__ void cpasync16(u32 d, const void* s){
    asm volatile("cp.async.cg.shared.global [%0], [%1], 16;"::"r"(d),"l"(s):"memory");}
#define CP_COMMIT asm volatile("cp.async.commit_group;":::"memory")
#define CP_WAIT(n) asm volatile("cp.async.wait_group %0;"::"n"(n):"memory")
#define LDS128(r, ad) asm volatile("ld.shared.v4.u32 {%0,%1,%2,%3},[%4];" \
  : "=r"((r)[0]),"=r"((r)[1]),"=r"((r)[2]),"=r"((r)[3]) : "r"(ad))
#define STS64(ad, x, y) asm volatile("st.shared.v2.u32 [%0],{%1,%2};" :: "r"(ad),"r"(x),"r"(y) : "memory")
#define STS32(ad, x) asm volatile("st.shared.u32 [%0],%1;" :: "r"(ad),"r"(x) : "memory")
__device__ __forceinline__ float sigm(float x){return 1.f/(1.f+__expf(-x));}

__global__ void __launch_bounds__(TPB,2) gvp_kernel(
    const float* __restrict__ s_g, const float* __restrict__ V_g,
    const float* __restrict__ Wmb, const float* __restrict__ Wgb,
    float* __restrict__ out, int N)
{
    extern __shared__ char smc[];
    const u32 smb = smem_u32(smc);
    const int t = threadIdx.x, lane = t&31, w = t>>5;     // 8 warps
    const int wm = w>>2, wn = w&3;     // main GEMM: warp tile 32 rows x 64 cols
    const int gm = w>>1, gn = w&1;     // V_h / gate / V_mu: warp = 16 rows x 16 cols
    const int r7 = lane>>2, c4 = lane&3;
    const int node0 = blockIdx.x*64;

    // A-staging producer: f = t + 256*h (h=0..1) -> (row = f>>3, k4 = t&7)
    const int ak4 = t&7;

    // ---- prologue ----
    if (t < 64) ((float4*)(smc+S_BIAS))[t] = ((const float4*)Wmb)[t];
    if (t >= 64 && t < 72) ((float4*)(smc+S_WGB))[t-64] = ((const float4*)Wgb)[t-64];
    #pragma unroll
    for (int q=0;q<8;q++)   // B chunk0 -> B0 (lands during V_h phase)
        cpasync16(smb + S_B0 + (t+256*q)*16, g_Bm + (t+256*q)*4);
    CP_COMMIT;

    // V scatter into 3 component A-frag tiles (64 nodes x 32 v)
    const u32 vtOff[3] = {S_VT0, S_VT1, S_VT2};
    #pragma unroll
    for (int q=0;q<6;q++){
        int g = t + 256*q, node = g/24, jj = g - node*24;
        float4 v4 = ((const float4*)V_g)[(size_t)(node0+node)*24 + jj];
        float vv[4] = {v4.x, v4.y, v4.z, v4.w};
        int mt = node>>4, rt = node&15;
        #pragma unroll
        for (int e=0;e<4;e++){
            int f = jj*4+e, vi = f/3, comp = f - vi*3;
            int lp = (rt&7)*4 + (vi&3);
            int jq = ((rt>>3)&1) + ((vi&4)?2:0);
            *(u32*)(smc + vtOff[comp] + (((mt*4+(vi>>3))*32 + lp)*4 + jq)*4) = rna(vv[e]);
        }
    }
    // A chunk0 prefetch (coalesced LDG.128, 2 per thread)
    float4 apf[2];
    #pragma unroll
    for (int h=0;h<2;h++)
        apf[h] = *(const float4*)(s_g + (size_t)(node0+((t+256*h)>>3))*256 + ak4*4);
    __syncthreads();

    // ---- V_h mma: warp (gm,gn): rows gm*16..+15, n-tiles gn*2..+1 (B via LDG, L2-hot) ----
    float vh[3][2][4];
    #pragma unroll
    for(int c=0;c<3;c++)for(int n2=0;n2<2;n2++)for(int e=0;e<4;e++) vh[c][n2][e]=0.f;
    #pragma unroll
    for (int c=0;c<3;c++)
    #pragma unroll
    for (int ks=0;ks<4;ks++){
        u32 a[4]; LDS128(a, smb + vtOff[c] + ((gm*4+ks)*32+lane)*16);
        #pragma unroll
        for (int n2=0;n2<2;n2++){
            float4 bq4 = ((const float4*)g_Bh)[((gn*2+n2)*2+(ks>>1))*32+lane];
            const u32* bq = (const u32*)&bq4;
            mma8(vh[c][n2], a, bq[(ks&1)*2], bq[(ks&1)*2+1]);
        }
    }
    // norm -> sh regs (chunk-8 A) + V_h tf32 frag tiles
    u32 shq[8];
    #pragma unroll
    for (int n2=0;n2<2;n2++)
    #pragma unroll
    for (int e=0;e<4;e++){
        float x=vh[0][n2][e], y=vh[1][n2][e], z=vh[2][n2][e];
        shq[n2*4+e] = rna(fmaxf(sqrtf(x*x+y*y+z*z), 1e-4f));
        int h = (gn*2+n2)*8 + 2*c4 + (e&1);
        int rt = r7 + ((e>>1)<<3);
        int lp = (rt&7)*4 + (h&3);
        int jq = ((rt>>3)&1) + ((h&4)?2:0);
        u32 idx = (((gm*4+(h>>3))*32 + lp)*4 + jq)*4;
        *(u32*)(smc + S_VH        + idx) = rna(x);
        *(u32*)(smc + S_VH + 8192 + idx) = rna(y);
        *(u32*)(smc + S_VH + 16384 + idx) = rna(z);
    }
    __syncthreads();   // V-tile reads done; S_A0/S_A1/S_B1 now free

    // ---- pre-stage chunk 0 A, prefetch chunk 1 A ----
    #pragma unroll
    for (int h=0;h<2;h++){
        int row = (t+256*h)>>3;
        int mt = row>>4, rt = row&15;
        int jq = ((rt>>3)&1) + ((ak4&1)?2:0);
        float vv[4] = {apf[h].x, apf[h].y, apf[h].z, apf[h].w};
        u32 base = smb + S_A0 + (((mt*4+(ak4>>1))*32 + (rt&7)*4)*4 + jq)*4;
        #pragma unroll
        for (int s=0;s<4;s++){
            int e = (s + ak4 + rt) & 3;
            STS32(base + e*16, rna(vv[e]));
        }
    }
    #pragma unroll
    for (int h=0;h<2;h++)
        apf[h] = *(const float4*)(s_g + (size_t)(node0+((t+256*h)>>3))*256 + 32 + ak4*4);
    CP_WAIT(0);        // B0 landed
    __syncthreads();

    // ---- main GEMM: 9 chunks, warp tile 32x64, overlapped staging ----
    float acc[2][8][4];
    #pragma unroll
    for(int i=0;i<2;i++)for(int j=0;j<8;j++)for(int e=0;e<4;e++) acc[i][j][e]=0.f;

    for (int c=0;c<9;c++){
        int buf = c&1;
        u32 aOff = buf? S_A1:S_A0, bRd  = buf? S_B1:S_B0;
        u32 aNxt = buf? S_A0:S_A1, bNxt = buf? S_B0:S_B1;

        if (c < 7){
            #pragma unroll
            for (int h=0;h<2;h++){
                int row = (t+256*h)>>3;
                int mt = row>>4, rt = row&15;
                int jq = ((rt>>3)&1) + ((ak4&1)?2:0);
                float vv[4] = {apf[h].x, apf[h].y, apf[h].z, apf[h].w};
                u32 base = smb + aNxt + (((mt*4+(ak4>>1))*32 + (rt&7)*4)*4 + jq)*4;
                #pragma unroll
                for (int s=0;s<4;s++){
                    int e = (s + ak4 + rt) & 3;
                    STS32(base + e*16, rna(vv[e]));
                }
            }
        } else if (c == 7){   // chunk 8 = s_h from regs
            #pragma unroll
            for (int n2=0;n2<2;n2++)
            #pragma unroll
            for (int e=0;e<4;e++){
                int h = (gn*2+n2)*8 + 2*c4 + (e&1);
                int rt = r7 + ((e>>1)<<3);
                int lp = (rt&7)*4 + (h&3);
                int jq = ((rt>>3)&1) + ((h&4)?2:0);
                *(u32*)(smc + aNxt + (((gm*4+(h>>3))*32 + lp)*4 + jq)*4) = shq[n2*4+e];
            }
        }
        if (c < 6){
            #pragma unroll
            for (int h=0;h<2;h++)
                apf[h] = *(const float4*)(s_g + (size_t)(node0+((t+256*h)>>3))*256 + (c+2)*32 + ak4*4);
        }
        if (c < 8){
            const u32* src = g_Bm + (c+1)*8192;
            #pragma unroll
            for (int q=0;q<8;q++)
                cpasync16(smb + bNxt + (t+256*q)*16, src + (t+256*q)*4);
            CP_COMMIT;
        }

        // -- compute chunk c: 32x64 tile, 64 mma --
        #pragma unroll
        for (int kh=0;kh<2;kh++){
            u32 b[8][4];
            #pragma unroll
            for (int j2=0;j2<8;j2++)
                LDS128(b[j2], smb + bRd + (((wn*8+j2)*2+kh)*32+lane)*16);
            #pragma unroll
            for (int ks2=0;ks2<2;ks2++){
                int ks = kh*2+ks2;
                u32 a[2][4];
                #pragma unroll
                for (int i=0;i<2;i++)
                    LDS128(a[i], smb + aOff + (((wm*2+i)*4+ks)*32+lane)*16);
                #pragma unroll
                for (int i=0;i<2;i++)
                    #pragma unroll
                    for (int j2=0;j2<8;j2++)
                        mma8(acc[i][j2], a[i], b[j2][ks2*2], b[j2][ks2*2+1]);
            }
        }
        if (c < 8) CP_WAIT(0);
        __syncthreads();
    }

    // ---- epilogue: relu store + sigma frags ----
    float2 bi[8];
    #pragma unroll
    for (int j2=0;j2<8;j2++)
        bi[j2] = *(const float2*)(smc + S_BIAS + (wn*64 + j2*8 + c4*2)*4);

    #pragma unroll
    for (int i=0;i<2;i++)
    #pragma unroll
    for (int j2=0;j2<8;j2++){
        int C = wn*64 + j2*8 + c4*2;
        size_t R = (size_t)node0 + wm*32 + i*16 + r7;
        float m0=acc[i][j2][0]+bi[j2].x, m1=acc[i][j2][1]+bi[j2].y;
        float m2=acc[i][j2][2]+bi[j2].x, m3=acc[i][j2][3]+bi[j2].y;
        float2 o0 = {fmaxf(m0,0.f), fmaxf(m1,0.f)};
        float2 o1 = {fmaxf(m2,0.f), fmaxf(m3,0.f)};
        *(float2*)(out + R*256 + C) = o0;
        *(float2*)(out + (R+8)*256 + C) = o1;
        u32 s0=rna(sigm(m0)), s1=rna(sigm(m1)), s2=rna(sigm(m2)), s3=rna(sigm(m3));
        int kseq = C>>3, c8 = C&7, mt = wm*2+i;
        u32 a0 = smb + S_SIG + ((u32)((mt*32+kseq)*32 + r7*4 + (c8&3)))*16 + ((c8&4)?8:0);
        STS64(a0, s0, s2);
        int c8b = c8+1;
        u32 a1 = smb + S_SIG + ((u32)((mt*32+kseq)*32 + r7*4 + (c8b&3)))*16 + ((c8b&4)?8:0);
        STS64(a1, s1, s3);
    }
    __syncthreads();

    // gate GEMM: [64x32] = sigma[64x256] @ Wg^T; warp (gm,gn); B via LDG (L2-hot)
    float gacc[2][4];
    #pragma unroll
    for(int n2=0;n2<2;n2++)for(int e=0;e<4;e++) gacc[n2][e]=0.f;
    for (int kc=0;kc<8;kc++){
        #pragma unroll
        for (int kh=0;kh<2;kh++){
            float4 b4[2];
            #pragma unroll
            for (int n2=0;n2<2;n2++)
                b4[n2] = ((const float4*)g_Bg)[kc*256 + (((gn*2+n2)*2+kh)*32+lane)];
            #pragma unroll
            for (int ks2=0;ks2<2;ks2++){
                int kseq = kc*4 + kh*2 + ks2;
                u32 a[4]; LDS128(a, smb + S_SIG + ((gm*32+kseq)*32+lane)*16);
                #pragma unroll
                for (int n2=0;n2<2;n2++){
                    const u32* bb = (const u32*)&b4[n2];
                    mma8(gacc[n2], a, bb[ks2*2], bb[ks2*2+1]);
                }
            }
        }
    }
    // V_mu mma from VH frag tiles; B via LDG
    float vm[3][2][4];
    #pragma unroll
    for(int c=0;c<3;c++)for(int n2=0;n2<2;n2++)for(int e=0;e<4;e++) vm[c][n2][e]=0.f;
    #pragma unroll
    for (int c3=0;c3<3;c3++)
    #pragma unroll
    for (int ks=0;ks<4;ks++){
        u32 a[4]; LDS128(a, smb + S_VH + c3*8192 + ((gm*4+ks)*32+lane)*16);
        #pragma unroll
        for (int n2=0;n2<2;n2++){
            float4 bq4 = ((const float4*)g_Bmu)[((gn*2+n2)*2+(ks>>1))*32+lane];
            const u32* bq = (const u32*)&bq4;
            mma8(vm[c3][n2], a, bq[(ks&1)*2], bq[(ks&1)*2+1]);
        }
    }
    // final: V_dash = sigmoid(gate logits + b) * V_mu
    #pragma unroll
    for (int n2=0;n2<2;n2++){
        int m0c = (gn*2+n2)*8 + c4*2;
        float wg0 = *(const float*)(smc + S_WGB + m0c*4);
        float wg1 = *(const float*)(smc + S_WGB + (m0c+1)*4);
        #pragma unroll
        for (int h2=0;h2<2;h2++){
            int e0 = h2*2;
            float g0 = sigm(gacc[n2][e0]   + wg0);
            float g1 = sigm(gacc[n2][e0+1] + wg1);
            size_t node = (size_t)node0 + gm*16 + r7 + h2*8;
            float* p = out + (size_t)N*256 + node*96 + m0c*3;
            float2 q0 = {g0*vm[0][n2][e0],   g0*vm[1][n2][e0]};
            float2 q1 = {g0*vm[2][n2][e0],   g1*vm[0][n2][e0+1]};
            float2 q2 = {g1*vm[1][n2][e0+1], g1*vm[2][n2][e0+1]};
            *(float2*)p = q0; *(float2*)(p+2) = q1; *(float2*)(p+4) = q2;
        }
    }
}

extern "C" void kernel_launch(void* const* d_in, const int* in_sizes, int n_in,
                              void* d_out, int out_size) {
    const float* s   = (const float*)d_in[0];
    const float* V   = (const float*)d_in[1];
    const float* Wh  = (const float*)d_in[2];
    const float* Wmu = (const float*)d_in[3];
    const float* Wm  = (const float*)d_in[4];
    const float* Wmb = (const float*)d_in[5];
    const float* Wg  = (const float*)d_in[6];
    const float* Wgb = (const float*)d_in[7];
    float* out = (float*)d_out;
    const int N = in_sizes[0] / 256;

    cudaFuncSetAttribute(gvp_kernel, cudaFuncAttributeMaxDynamicSharedMemorySize, SMEM_TOTAL);
    prep<<<(83968+255)/256, 256>>>(Wm, Wg, Wh, Wmu);
    gvp_kernel<<<N/64, TPB, SMEM_TOTAL>>>(s, V, Wmb, Wgb, out, N);
}